// round 10
// baseline (speedup 1.0000x reference)
#include <cuda_runtime.h>
#include <cuda_bf16.h>
#include <cuda_fp16.h>

#define NMAX 100000
#define EMAX 1600000
#define GMAX 1000
#define EPS 1e-5f

// ---- scratch (static device globals; no allocation) ----
// Self-cleaning invariants (hold at entry of every kernel_launch call):
//   g_hist  == 0   (load-time init; re-zeroed by scan_p3 after consumption)
//   g_stats == 0   (load-time init; re-zeroed by scan_p2 each launch before layers)
__device__ int    g_hist[NMAX];
__device__ int    g_rp  [NMAX + 1];   // CSR row ptr (by dst)
__device__ int    g_pos [NMAX];       // fill cursor
__device__ int    g_ci  [EMAX];       // CSR col idx (src)
__device__ int    g_gp  [GMAX + 1];   // per-graph node ranges
__device__ __align__(16) int g_tsum[4096];  // scan partials
__device__ __align__(16) __half g_h16[NMAX * 32];
__device__ __align__(16) __half g_x1 [NMAX * 32];  // raw linear outputs (pre-BN), fp16
__device__ __align__(16) __half g_x2 [NMAX * 32];
__device__ __align__(16) __half g_x3 [NMAX * 32];
__device__ float  g_x4  [NMAX];
__device__ float  g_z   [NMAX];       // folded BN(x3)·W3
__device__ double g_stats[4 * 64];    // per layer: [0..31]=sum, [32..63]=sumsq

// ---- fused: histogram of dst + convert h (fp32 -> fp16) ----
__global__ void hist_h2half_kernel(const int* __restrict__ dst, int* __restrict__ hist, int E,
                                   const float* __restrict__ h, __half* __restrict__ h16, int n8) {
    int i = blockIdx.x * blockDim.x + threadIdx.x;
    if (i < E) atomicAdd(&hist[dst[i]], 1);
    if (i < n8) {
        const float4* hf = (const float4*)h;
        float4 a = hf[2 * i], b = hf[2 * i + 1];
        __half2 p0 = __floats2half2_rn(a.x, a.y);
        __half2 p1 = __floats2half2_rn(a.z, a.w);
        __half2 p2 = __floats2half2_rn(b.x, b.y);
        __half2 p3 = __floats2half2_rn(b.z, b.w);
        uint4 u;
        u.x = *(unsigned*)&p0; u.y = *(unsigned*)&p1;
        u.z = *(unsigned*)&p2; u.w = *(unsigned*)&p3;
        ((uint4*)h16)[i] = u;
    }
}

// ---- 3-phase exclusive scan over n entries -> rp[0..n], pos[0..n-1] ----
#define SCAN_THREADS 4096
__global__ void scan_p1(const int* __restrict__ in, int* __restrict__ tsum, int n, int chunk) {
    int t = blockIdx.x * blockDim.x + threadIdx.x;
    int begin = t * chunk, end = min(begin + chunk, n);
    int s = 0;
    for (int i = begin; i < end; i++) s += in[i];
    tsum[t] = s;
}
// also zeroes g_stats for this launch (256 doubles)
__global__ void scan_p2(int* __restrict__ tsum, double* __restrict__ stats) {
    __shared__ int wsum[32];
    int t = threadIdx.x;
    if (t < 256) stats[t] = 0.0;
    int lane = t & 31, wid = t >> 5;
    int4 v = ((const int4*)tsum)[t];
    int s = ((v.x + v.y) + (v.z + v.w));
    int sc = s;
#pragma unroll
    for (int off = 1; off < 32; off <<= 1) {
        int u = __shfl_up_sync(0xffffffffu, sc, off);
        if (lane >= off) sc += u;
    }
    if (lane == 31) wsum[wid] = sc;
    __syncthreads();
    if (wid == 0) {
        int ws = wsum[lane];
        int wsc = ws;
#pragma unroll
        for (int off = 1; off < 32; off <<= 1) {
            int u = __shfl_up_sync(0xffffffffu, wsc, off);
            if (lane >= off) wsc += u;
        }
        wsum[lane] = wsc - ws;
    }
    __syncthreads();
    int base = wsum[wid] + (sc - s);
    int4 o;
    o.x = base;         base += v.x;
    o.y = base;         base += v.y;
    o.z = base;         base += v.z;
    o.w = base;
    ((int4*)tsum)[t] = o;
}
// consumes hist and re-zeroes it (self-cleaning for the next launch)
__global__ void scan_p3(int* __restrict__ in, const int* __restrict__ tsum,
                        int* __restrict__ out, int* __restrict__ pos, int n, int chunk) {
    int t = blockIdx.x * blockDim.x + threadIdx.x;
    int begin = t * chunk, end = min(begin + chunk, n);
    int off = tsum[t];
    for (int i = begin; i < end; i++) {
        int v = in[i];
        in[i] = 0;
        out[i] = off;
        pos[i] = off;
        off += v;
    }
    if (end == n && begin < n) out[n] = off;
}

// ---- fill CSR: slot per edge via atomic cursor ----
__global__ void fill_kernel(const int* __restrict__ src, const int* __restrict__ dst,
                            int* __restrict__ pos, int* __restrict__ ci, int E) {
    int e = blockIdx.x * blockDim.x + threadIdx.x;
    if (e < E) {
        int slot = atomicAdd(&pos[dst[e]], 1);
        ci[slot] = src[e];
    }
}

// ---- graph ranges via boundary scatter (gid sorted) ----
__global__ void graph_ptr_kernel(const int* __restrict__ gid, int* __restrict__ gp, int n, int G) {
    int v = blockIdx.x * blockDim.x + threadIdx.x;
    if (v > n) return;
    int g0 = (v == 0) ? -1 : gid[v - 1];
    int g1 = (v == n) ? G  : gid[v];
    for (int g = g0 + 1; g <= g1; g++) gp[g] = v;
}

// ---- fused 32->32 layer, fp16 in/out, half2 BN+accumulate, fp32 stat partials ----
// warp per node; lane = (edge_sub eq = lane>>2, chan_quad cq = lane&3)
// each lane loads 16B = 8 fp16 channels; one warp LDG covers 8 edges.
template <bool BN>
__global__ void __launch_bounds__(512, 2)
gcn_layer32h(const __half* __restrict__ x, const int* __restrict__ rp,
             const int* __restrict__ ci, const float* __restrict__ W,
             const float* __restrict__ bias,
             const double* __restrict__ statsIn,
             const float* __restrict__ gIn, const float* __restrict__ bIn,
             __half* __restrict__ out, int n, double* __restrict__ statsOut) {
    __shared__ float  Ws[32 * 32];
    __shared__ float  bs[32];
    __shared__ float  As[32], Bs[32];
    __shared__ __align__(16) float xv[16][32];
    __shared__ double ssum[32], ssq[32];
    int t = threadIdx.x;
    for (int i = t; i < 1024; i += 512) Ws[i] = W[i];
    if (t < 32) {
        bs[t] = bias[t];
        ssum[t] = 0.0; ssq[t] = 0.0;
        if (BN) {
            double m   = statsIn[t] / (double)n;
            double var = statsIn[32 + t] / (double)n - m * m;
            float  rs  = rsqrtf((float)var + EPS);
            float  A   = gIn[t] * rs;
            As[t] = A;
            Bs[t] = bIn[t] - (float)m * A;
        }
    }
    __syncthreads();
    int w = t >> 5, lane = t & 31;
    int eq = lane >> 2, cq = lane & 3;
    __half2 A2[4], B2[4];
    const __half2 z2 = __floats2half2_rn(0.f, 0.f);
    if (BN) {
#pragma unroll
        for (int k = 0; k < 4; k++) {
            A2[k] = __floats2half2_rn(As[cq * 8 + 2 * k], As[cq * 8 + 2 * k + 1]);
            B2[k] = __floats2half2_rn(Bs[cq * 8 + 2 * k], Bs[cq * 8 + 2 * k + 1]);
        }
    }
    int warpsTotal = gridDim.x * 16;
    int wg = blockIdx.x * 16 + w;
    float fsum = 0.f, fsq = 0.f;
    for (int v = wg; v < n; v += warpsTotal) {
        int beg = __ldg(&rp[v]), end = __ldg(&rp[v + 1]);
        float acc[8];
#pragma unroll
        for (int k = 0; k < 8; k++) acc[k] = 0.f;

        auto accum1 = [&](uint4 u) {
            const unsigned* a = &u.x;
#pragma unroll
            for (int k = 0; k < 4; k++) {
                __half2 p = *(const __half2*)&a[k];
                if (BN) p = __hmax2(__hfma2(p, A2[k], B2[k]), z2);
                float2 f = __half22float2(p);
                acc[2 * k]     += f.x;
                acc[2 * k + 1] += f.y;
            }
        };

        int j = beg;
        for (; j + 16 <= end; j += 16) {
            int s0 = __ldg(&ci[j + eq]);
            int s1 = __ldg(&ci[j + 8 + eq]);
            uint4 u0 = __ldg((const uint4*)(x + (size_t)s0 * 32) + cq);
            uint4 u1 = __ldg((const uint4*)(x + (size_t)s1 * 32) + cq);
            const unsigned* a0 = &u0.x;
            const unsigned* a1 = &u1.x;
#pragma unroll
            for (int k = 0; k < 4; k++) {
                __half2 p0 = *(const __half2*)&a0[k];
                __half2 p1 = *(const __half2*)&a1[k];
                if (BN) {
                    p0 = __hmax2(__hfma2(p0, A2[k], B2[k]), z2);
                    p1 = __hmax2(__hfma2(p1, A2[k], B2[k]), z2);
                }
                float2 f = __half22float2(__hadd2(p0, p1));
                acc[2 * k]     += f.x;
                acc[2 * k + 1] += f.y;
            }
        }
        if (j + 8 <= end) {
            int s0 = __ldg(&ci[j + eq]);
            uint4 u0 = __ldg((const uint4*)(x + (size_t)s0 * 32) + cq);
            accum1(u0);
            j += 8;
        }
        if (j + eq < end) {
            int s0 = __ldg(&ci[j + eq]);
            uint4 u0 = __ldg((const uint4*)(x + (size_t)s0 * 32) + cq);
            accum1(u0);
        }
        // reduce over 8 edge subgroups (lane bits 2,3,4)
#pragma unroll
        for (int k = 0; k < 8; k++) {
            acc[k] += __shfl_xor_sync(0xffffffffu, acc[k], 4);
            acc[k] += __shfl_xor_sync(0xffffffffu, acc[k], 8);
            acc[k] += __shfl_xor_sync(0xffffffffu, acc[k], 16);
        }
        float inv = 1.0f / fmaxf((float)(end - beg), 1.0f);
        if (eq == 0) {
            *(float4*)&xv[w][cq * 8]     = make_float4(acc[0]*inv, acc[1]*inv, acc[2]*inv, acc[3]*inv);
            *(float4*)&xv[w][cq * 8 + 4] = make_float4(acc[4]*inv, acc[5]*inv, acc[6]*inv, acc[7]*inv);
        }
        __syncwarp();
        float o = bs[lane];
#pragma unroll
        for (int i = 0; i < 32; i++) o = fmaf(xv[w][i], Ws[i * 32 + lane], o);
        __syncwarp();
        fsum += o;
        fsq  = fmaf(o, o, fsq);
        float onb = __shfl_xor_sync(0xffffffffu, o, 1);
        if ((lane & 1) == 0) {
            __half2 hv = __floats2half2_rn(o, onb);
            ((__half2*)out)[(size_t)v * 16 + (lane >> 1)] = hv;
        }
    }
    atomicAdd(&ssum[lane], (double)fsum);
    atomicAdd(&ssq[lane],  (double)fsq);
    __syncthreads();
    if (t < 32) {
        atomicAdd(&statsOut[t],      ssum[t]);
        atomicAdd(&statsOut[32 + t], ssq[t]);
    }
}

// ---- fold: z[v] = BN(x3[v]) . W3  (warp per node, lane=channel) ----
__global__ void fold_kernel(const __half* __restrict__ x3,
                            const double* __restrict__ statsIn,
                            const float* __restrict__ gIn, const float* __restrict__ bIn,
                            const float* __restrict__ W3,
                            float* __restrict__ z, int n) {
    __shared__ float As[32], Bs[32], Wsh[32];
    int t = threadIdx.x;
    if (t < 32) {
        double m   = statsIn[t] / (double)n;
        double var = statsIn[32 + t] / (double)n - m * m;
        float  rs  = rsqrtf((float)var + EPS);
        float  A   = gIn[t] * rs;
        As[t] = A;
        Bs[t] = bIn[t] - (float)m * A;
        Wsh[t] = W3[t];
    }
    __syncthreads();
    int w = t >> 5, lane = t & 31;
    int v = blockIdx.x * 8 + w;
    if (v >= n) return;
    float val = __half2float(x3[(size_t)v * 32 + lane]);
    val = fmaxf(fmaf(As[lane], val, Bs[lane]), 0.f) * Wsh[lane];
#pragma unroll
    for (int off = 16; off; off >>= 1) val += __shfl_down_sync(0xffffffffu, val, off);
    if (lane == 0) z[v] = val;
}

// ---- layer 4: scalar mean-gather of z + bias + stats (fp32 partials) ----
__global__ void __launch_bounds__(512, 2)
layer4_kernel(const float* __restrict__ z, const int* __restrict__ rp,
              const int* __restrict__ ci, const float* __restrict__ b3,
              float* __restrict__ out, int n, double* __restrict__ statsOut) {
    __shared__ double ssum, ssq;
    int t = threadIdx.x;
    if (t == 0) { ssum = 0.0; ssq = 0.0; }
    __syncthreads();
    int w = t >> 5, lane = t & 31;
    int warpsTotal = gridDim.x * 16;
    int wg = blockIdx.x * 16 + w;
    float bias = b3[0];
    float fsum = 0.f, fsq = 0.f;
    for (int v = wg; v < n; v += warpsTotal) {
        int beg = __ldg(&rp[v]), end = __ldg(&rp[v + 1]);
        float s = 0.f;
        for (int j = beg + lane; j < end; j += 32) s += z[__ldg(&ci[j])];
#pragma unroll
        for (int off = 16; off; off >>= 1) s += __shfl_down_sync(0xffffffffu, s, off);
        if (lane == 0) {
            float o = s / fmaxf((float)(end - beg), 1.0f) + bias;
            out[v] = o;
            fsum += o;
            fsq  = fmaf(o, o, fsq);
        }
    }
    if (lane == 0) {
        atomicAdd(&ssum, (double)fsum);
        atomicAdd(&ssq,  (double)fsq);
    }
    __syncthreads();
    if (t == 0) {
        atomicAdd(&statsOut[0],  ssum);
        atomicAdd(&statsOut[32], ssq);
    }
}

// ---- fused per-graph mean pool (BN on the fly; x1..x3 fp16) + MLP head ----
__global__ void pool_mlp_kernel(const float* __restrict__ h,  const __half* __restrict__ x1,
                                const __half* __restrict__ x2, const __half* __restrict__ x3,
                                const float* __restrict__ x4, const int* __restrict__ gp,
                                const double* __restrict__ stats,
                                const float* __restrict__ g0, const float* __restrict__ be0,
                                const float* __restrict__ g1, const float* __restrict__ be1,
                                const float* __restrict__ g2, const float* __restrict__ be2,
                                const float* __restrict__ g3, const float* __restrict__ be3,
                                const float* __restrict__ W0, const float* __restrict__ b0,
                                const float* __restrict__ W1, const float* __restrict__ b1,
                                const float* __restrict__ W2, const float* __restrict__ b2,
                                float* __restrict__ out, int n) {
    __shared__ float As[97], Bs[97];
    __shared__ float hr[129];
    __shared__ float l0[128];
    __shared__ float l1[64];
    int t = threadIdx.x;
    if (t < 97) {
        int layer = (t < 96) ? (t >> 5) : 3;
        int c     = (t < 96) ? (t & 31) : 0;
        const double* st = stats + layer * 64;
        const float* gg = (layer == 0) ? g0 : (layer == 1) ? g1 : (layer == 2) ? g2 : g3;
        const float* bb = (layer == 0) ? be0 : (layer == 1) ? be1 : (layer == 2) ? be2 : be3;
        double m   = st[c] / (double)n;
        double var = st[32 + c] / (double)n - m * m;
        float  rs  = rsqrtf((float)var + EPS);
        float  A   = gg[c] * rs;
        As[t] = A;
        Bs[t] = bb[c] - (float)m * A;
    }
    __syncthreads();
    int g = blockIdx.x;
    int beg = gp[g], end = gp[g + 1];
    float inv = 1.0f / fmaxf((float)(end - beg), 1.0f);
    int w = t >> 5, c = t & 31;
    {
        float s = 0.f;
        if (w == 0) {
            int v = beg;
            for (; v + 4 <= end; v += 4) {
                float a = h[v * 32 + c],       b = h[(v + 1) * 32 + c];
                float d = h[(v + 2) * 32 + c], e = h[(v + 3) * 32 + c];
                s += (a + b) + (d + e);
            }
            for (; v < end; v++) s += h[v * 32 + c];
        } else {
            const __half* p = (w == 1) ? x1 : (w == 2) ? x2 : x3;
            float A = As[(w - 1) * 32 + c];
            float B = Bs[(w - 1) * 32 + c];
            int v = beg;
            for (; v + 4 <= end; v += 4) {
                float a = __half2float(p[(size_t)v * 32 + c]);
                float b = __half2float(p[(size_t)(v + 1) * 32 + c]);
                float d = __half2float(p[(size_t)(v + 2) * 32 + c]);
                float e = __half2float(p[(size_t)(v + 3) * 32 + c]);
                a = fmaxf(fmaf(A, a, B), 0.f); b = fmaxf(fmaf(A, b, B), 0.f);
                d = fmaxf(fmaf(A, d, B), 0.f); e = fmaxf(fmaf(A, e, B), 0.f);
                s += (a + b) + (d + e);
            }
            for (; v < end; v++) s += fmaxf(fmaf(A, __half2float(p[(size_t)v * 32 + c]), B), 0.f);
        }
        hr[t] = s * inv;
    }
    if (t == 0) {
        float A = As[96], B = Bs[96];
        float s = 0.f;
        int v = beg;
        for (; v + 4 <= end; v += 4) {
            float a = fmaxf(fmaf(A, x4[v], B), 0.f);
            float b = fmaxf(fmaf(A, x4[v + 1], B), 0.f);
            float d = fmaxf(fmaf(A, x4[v + 2], B), 0.f);
            float e = fmaxf(fmaf(A, x4[v + 3], B), 0.f);
            s += (a + b) + (d + e);
        }
        for (; v < end; v++) s += fmaxf(fmaf(A, x4[v], B), 0.f);
        hr[128] = s * inv;
    }
    __syncthreads();
    {
        float acc = b0[t];
#pragma unroll 4
        for (int i = 0; i < 129; i++) acc = fmaf(hr[i], W0[i * 128 + t], acc);
        l0[t] = fmaxf(acc, 0.0f);
    }
    __syncthreads();
    if (t < 64) {
        float acc = b1[t];
#pragma unroll 4
        for (int i = 0; i < 128; i++) acc = fmaf(l0[i], W1[i * 64 + t], acc);
        l1[t] = fmaxf(acc, 0.0f);
    }
    __syncthreads();
    if (t == 0) {
        float acc = b2[0];
        for (int i = 0; i < 64; i++) acc = fmaf(l1[i], W2[i], acc);
        out[g] = acc;
    }
}

extern "C" void kernel_launch(void* const* d_in, const int* in_sizes, int n_in,
                              void* d_out, int out_size) {
    const float* h   = (const float*)d_in[0];
    const int*   src = (const int*)d_in[1];
    const int*   dst = (const int*)d_in[2];
    const int*   gid = (const int*)d_in[3];
    const int E = in_sizes[1];
    const int N = in_sizes[3];
    const int G = out_size;
    float* out = (float*)d_out;

    const float* cw[4]; const float* cb[4]; const float* bg[4]; const float* bb[4];
    for (int i = 0; i < 4; i++) {
        cw[i] = (const float*)d_in[4 + 4 * i + 0];
        cb[i] = (const float*)d_in[4 + 4 * i + 1];
        bg[i] = (const float*)d_in[4 + 4 * i + 2];
        bb[i] = (const float*)d_in[4 + 4 * i + 3];
    }
    const float* W0 = (const float*)d_in[20];
    const float* b0 = (const float*)d_in[21];
    const float* W1 = (const float*)d_in[22];
    const float* b1 = (const float*)d_in[23];
    const float* W2 = (const float*)d_in[24];
    const float* b2 = (const float*)d_in[25];

    int *hist, *rp, *pos, *ci, *gp, *tsum;
    __half *h16, *x1, *x2, *x3;
    float *x4, *z;
    double *stats;
    cudaGetSymbolAddress((void**)&hist,  g_hist);
    cudaGetSymbolAddress((void**)&rp,    g_rp);
    cudaGetSymbolAddress((void**)&pos,   g_pos);
    cudaGetSymbolAddress((void**)&ci,    g_ci);
    cudaGetSymbolAddress((void**)&gp,    g_gp);
    cudaGetSymbolAddress((void**)&tsum,  g_tsum);
    cudaGetSymbolAddress((void**)&h16,   g_h16);
    cudaGetSymbolAddress((void**)&x1,    g_x1);
    cudaGetSymbolAddress((void**)&x2,    g_x2);
    cudaGetSymbolAddress((void**)&x3,    g_x3);
    cudaGetSymbolAddress((void**)&x4,    g_x4);
    cudaGetSymbolAddress((void**)&z,     g_z);
    cudaGetSymbolAddress((void**)&stats, g_stats);

    const int T = 256;
    const int n8 = N * 4;  // N*32/8 uint4-sized conversion items

    // ---- CSR build (g_hist and g_stats arrive zeroed: load-init / self-cleaned) ----
    int combo = max(E, n8);
    hist_h2half_kernel<<<(combo + T - 1) / T, T>>>(dst, hist, E, h, h16, n8);
    {
        int chunk = (N + SCAN_THREADS - 1) / SCAN_THREADS;
        scan_p1<<<SCAN_THREADS / 256, 256>>>(hist, tsum, N, chunk);
        scan_p2<<<1, 1024>>>(tsum, stats);               // + zero stats
        scan_p3<<<SCAN_THREADS / 256, 256>>>(hist, tsum, rp, pos, N, chunk);  // + re-zero hist
    }
    fill_kernel<<<(E + T - 1) / T, T>>>(src, dst, pos, ci, E);

    // ---- GCN layers (layer1 is the 6th launch -> ncu capture target) ----
    const int LG = 296, LT = 512;
    gcn_layer32h<false><<<LG, LT>>>(h16, rp, ci, cw[0], cb[0],
                                    nullptr, nullptr, nullptr,
                                    x1, N, stats + 0 * 64);
    gcn_layer32h<true><<<LG, LT>>>(x1, rp, ci, cw[1], cb[1],
                                   stats + 0 * 64, bg[0], bb[0],
                                   x2, N, stats + 1 * 64);
    gcn_layer32h<true><<<LG, LT>>>(x2, rp, ci, cw[2], cb[2],
                                   stats + 1 * 64, bg[1], bb[1],
                                   x3, N, stats + 2 * 64);
    fold_kernel<<<(N + 7) / 8, 256>>>(x3, stats + 2 * 64, bg[2], bb[2], cw[3], z, N);
    layer4_kernel<<<LG, LT>>>(z, rp, ci, cb[3], x4, N, stats + 3 * 64);

    // ---- graph ranges + fused pool + MLP ----
    graph_ptr_kernel<<<(N + 1 + T - 1) / T, T>>>(gid, gp, N, G);
    pool_mlp_kernel<<<G, 128>>>(h, x1, x2, x3, x4, gp, stats,
                                bg[0], bb[0], bg[1], bb[1], bg[2], bb[2], bg[3], bb[3],
                                W0, b0, W1, b1, W2, b2, out, N);
}

// round 11
// speedup vs baseline: 1.1954x; 1.1954x over previous
#include <cuda_runtime.h>
#include <cuda_bf16.h>
#include <cuda_fp16.h>

#define NMAX 100000
#define EMAX 1600000
#define GMAX 1000
#define EPS 1e-5f
#define SBS 1024   // scan block size (one element per thread)

// ---- scratch (static device globals; no allocation) ----
// Self-cleaning invariants (hold at entry of every kernel_launch call):
//   g_hist  == 0   (load-time init; re-zeroed by scan_p3 after consumption)
//   g_stats == 0   (load-time init; re-zeroed by scan_p2 each launch before layers)
__device__ int    g_hist[NMAX];
__device__ int    g_rp  [NMAX + 1];   // CSR row ptr (by dst)
__device__ int    g_pos [NMAX];       // fill cursor
__device__ int    g_ci  [EMAX];       // CSR col idx (src)
__device__ int    g_gp  [GMAX + 1];   // per-graph node ranges
__device__ int    g_bsum[1024];       // per-block scan sums
__device__ __align__(16) __half g_h16[NMAX * 32];
__device__ __align__(16) __half g_x1 [NMAX * 32];  // raw linear outputs (pre-BN), fp16
__device__ __align__(16) __half g_x2 [NMAX * 32];
__device__ __align__(16) __half g_x3 [NMAX * 32];
__device__ float  g_x4  [NMAX];
__device__ float  g_z   [NMAX];       // folded BN(x3)·W3
__device__ double g_stats[4 * 64];    // per layer: [0..31]=sum, [32..63]=sumsq

// ---- fused: histogram of dst + convert h (fp32 -> fp16) ----
__global__ void hist_h2half_kernel(const int* __restrict__ dst, int* __restrict__ hist, int E,
                                   const float* __restrict__ h, __half* __restrict__ h16, int n8) {
    int i = blockIdx.x * blockDim.x + threadIdx.x;
    if (i < E) atomicAdd(&hist[dst[i]], 1);
    if (i < n8) {
        const float4* hf = (const float4*)h;
        float4 a = hf[2 * i], b = hf[2 * i + 1];
        __half2 p0 = __floats2half2_rn(a.x, a.y);
        __half2 p1 = __floats2half2_rn(a.z, a.w);
        __half2 p2 = __floats2half2_rn(b.x, b.y);
        __half2 p3 = __floats2half2_rn(b.z, b.w);
        uint4 u;
        u.x = *(unsigned*)&p0; u.y = *(unsigned*)&p1;
        u.z = *(unsigned*)&p2; u.w = *(unsigned*)&p3;
        ((uint4*)h16)[i] = u;
    }
}

// ---- coalesced 3-phase exclusive scan: one element per thread ----
// p1: per-block sums
__global__ void scan_p1(const int* __restrict__ in, int* __restrict__ bsum, int n) {
    __shared__ int ws[32];
    int i = blockIdx.x * SBS + threadIdx.x;
    int v = (i < n) ? in[i] : 0;
    int lane = threadIdx.x & 31, wid = threadIdx.x >> 5;
#pragma unroll
    for (int off = 16; off; off >>= 1) v += __shfl_down_sync(0xffffffffu, v, off);
    if (lane == 0) ws[wid] = v;
    __syncthreads();
    if (wid == 0) {
        int s = ws[lane];
#pragma unroll
        for (int off = 16; off; off >>= 1) s += __shfl_down_sync(0xffffffffu, s, off);
        if (lane == 0) bsum[blockIdx.x] = s;
    }
}
// p2: exclusive scan of block sums (nb <= 1024); also zeroes stats
__global__ void scan_p2(int* __restrict__ bsum, int nb, double* __restrict__ stats) {
    __shared__ int wsum[32];
    int t = threadIdx.x;
    if (t < 256) stats[t] = 0.0;
    int v = (t < nb) ? bsum[t] : 0;
    int lane = t & 31, wid = t >> 5;
    int sc = v;
#pragma unroll
    for (int off = 1; off < 32; off <<= 1) {
        int u = __shfl_up_sync(0xffffffffu, sc, off);
        if (lane >= off) sc += u;
    }
    if (lane == 31) wsum[wid] = sc;
    __syncthreads();
    if (wid == 0) {
        int ws = wsum[lane];
        int wsc = ws;
#pragma unroll
        for (int off = 1; off < 32; off <<= 1) {
            int u = __shfl_up_sync(0xffffffffu, wsc, off);
            if (lane >= off) wsc += u;
        }
        wsum[lane] = wsc - ws;
    }
    __syncthreads();
    int ex = wsum[wid] + sc - v;   // exclusive prefix
    if (t < nb) bsum[t] = ex;
}
// p3: block-level exclusive scan + offset; writes rp/pos; re-zeroes hist
__global__ void scan_p3(int* __restrict__ in, const int* __restrict__ bsum,
                        int* __restrict__ rp, int* __restrict__ pos, int n) {
    __shared__ int wsum[32];
    int t = threadIdx.x;
    int i = blockIdx.x * SBS + t;
    int v = (i < n) ? in[i] : 0;
    if (i < n) in[i] = 0;
    int lane = t & 31, wid = t >> 5;
    int sc = v;
#pragma unroll
    for (int off = 1; off < 32; off <<= 1) {
        int u = __shfl_up_sync(0xffffffffu, sc, off);
        if (lane >= off) sc += u;
    }
    if (lane == 31) wsum[wid] = sc;
    __syncthreads();
    if (wid == 0) {
        int ws = wsum[lane];
        int wsc = ws;
#pragma unroll
        for (int off = 1; off < 32; off <<= 1) {
            int u = __shfl_up_sync(0xffffffffu, wsc, off);
            if (lane >= off) wsc += u;
        }
        wsum[lane] = wsc - ws;
    }
    __syncthreads();
    int ex = wsum[wid] + sc - v;
    int off = bsum[blockIdx.x] + ex;
    if (i < n) {
        rp[i]  = off;
        pos[i] = off;
        if (i == n - 1) rp[n] = off + v;
    }
}

// ---- fill CSR: slot per edge via atomic cursor ----
__global__ void fill_kernel(const int* __restrict__ src, const int* __restrict__ dst,
                            int* __restrict__ pos, int* __restrict__ ci, int E) {
    int e = blockIdx.x * blockDim.x + threadIdx.x;
    if (e < E) {
        int slot = atomicAdd(&pos[dst[e]], 1);
        ci[slot] = src[e];
    }
}

// ---- graph ranges via boundary scatter (gid sorted) ----
__global__ void graph_ptr_kernel(const int* __restrict__ gid, int* __restrict__ gp, int n, int G) {
    int v = blockIdx.x * blockDim.x + threadIdx.x;
    if (v > n) return;
    int g0 = (v == 0) ? -1 : gid[v - 1];
    int g1 = (v == n) ? G  : gid[v];
    for (int g = g0 + 1; g <= g1; g++) gp[g] = v;
}

// ---- fused 32->32 layer, fp16 in/out, half2 BN+accumulate, fp32 stat partials ----
// warp per node; lane = (edge_sub eq = lane>>2, chan_quad cq = lane&3)
// each lane loads 16B = 8 fp16 channels; one warp LDG covers 8 edges.
template <bool BN>
__global__ void __launch_bounds__(512, 2)
gcn_layer32h(const __half* __restrict__ x, const int* __restrict__ rp,
             const int* __restrict__ ci, const float* __restrict__ W,
             const float* __restrict__ bias,
             const double* __restrict__ statsIn,
             const float* __restrict__ gIn, const float* __restrict__ bIn,
             __half* __restrict__ out, int n, double* __restrict__ statsOut) {
    __shared__ float  Ws[32 * 32];
    __shared__ float  bs[32];
    __shared__ float  As[32], Bs[32];
    __shared__ __align__(16) float xv[16][32];
    __shared__ double ssum[32], ssq[32];
    int t = threadIdx.x;
    for (int i = t; i < 1024; i += 512) Ws[i] = W[i];
    if (t < 32) {
        bs[t] = bias[t];
        ssum[t] = 0.0; ssq[t] = 0.0;
        if (BN) {
            double m   = statsIn[t] / (double)n;
            double var = statsIn[32 + t] / (double)n - m * m;
            float  rs  = rsqrtf((float)var + EPS);
            float  A   = gIn[t] * rs;
            As[t] = A;
            Bs[t] = bIn[t] - (float)m * A;
        }
    }
    __syncthreads();
    int w = t >> 5, lane = t & 31;
    int eq = lane >> 2, cq = lane & 3;
    __half2 A2[4], B2[4];
    const __half2 z2 = __floats2half2_rn(0.f, 0.f);
    if (BN) {
#pragma unroll
        for (int k = 0; k < 4; k++) {
            A2[k] = __floats2half2_rn(As[cq * 8 + 2 * k], As[cq * 8 + 2 * k + 1]);
            B2[k] = __floats2half2_rn(Bs[cq * 8 + 2 * k], Bs[cq * 8 + 2 * k + 1]);
        }
    }
    int warpsTotal = gridDim.x * 16;
    int wg = blockIdx.x * 16 + w;
    float fsum = 0.f, fsq = 0.f;
    for (int v = wg; v < n; v += warpsTotal) {
        int beg = __ldg(&rp[v]), end = __ldg(&rp[v + 1]);
        float acc[8];
#pragma unroll
        for (int k = 0; k < 8; k++) acc[k] = 0.f;

        auto accum1 = [&](uint4 u) {
            const unsigned* a = &u.x;
#pragma unroll
            for (int k = 0; k < 4; k++) {
                __half2 p = *(const __half2*)&a[k];
                if (BN) p = __hmax2(__hfma2(p, A2[k], B2[k]), z2);
                float2 f = __half22float2(p);
                acc[2 * k]     += f.x;
                acc[2 * k + 1] += f.y;
            }
        };

        int j = beg;
        for (; j + 16 <= end; j += 16) {
            int s0 = __ldg(&ci[j + eq]);
            int s1 = __ldg(&ci[j + 8 + eq]);
            uint4 u0 = __ldg((const uint4*)(x + (size_t)s0 * 32) + cq);
            uint4 u1 = __ldg((const uint4*)(x + (size_t)s1 * 32) + cq);
            const unsigned* a0 = &u0.x;
            const unsigned* a1 = &u1.x;
#pragma unroll
            for (int k = 0; k < 4; k++) {
                __half2 p0 = *(const __half2*)&a0[k];
                __half2 p1 = *(const __half2*)&a1[k];
                if (BN) {
                    p0 = __hmax2(__hfma2(p0, A2[k], B2[k]), z2);
                    p1 = __hmax2(__hfma2(p1, A2[k], B2[k]), z2);
                }
                float2 f = __half22float2(__hadd2(p0, p1));
                acc[2 * k]     += f.x;
                acc[2 * k + 1] += f.y;
            }
        }
        if (j + 8 <= end) {
            int s0 = __ldg(&ci[j + eq]);
            uint4 u0 = __ldg((const uint4*)(x + (size_t)s0 * 32) + cq);
            accum1(u0);
            j += 8;
        }
        if (j + eq < end) {
            int s0 = __ldg(&ci[j + eq]);
            uint4 u0 = __ldg((const uint4*)(x + (size_t)s0 * 32) + cq);
            accum1(u0);
        }
        // reduce over 8 edge subgroups (lane bits 2,3,4)
#pragma unroll
        for (int k = 0; k < 8; k++) {
            acc[k] += __shfl_xor_sync(0xffffffffu, acc[k], 4);
            acc[k] += __shfl_xor_sync(0xffffffffu, acc[k], 8);
            acc[k] += __shfl_xor_sync(0xffffffffu, acc[k], 16);
        }
        float inv = 1.0f / fmaxf((float)(end - beg), 1.0f);
        if (eq == 0) {
            *(float4*)&xv[w][cq * 8]     = make_float4(acc[0]*inv, acc[1]*inv, acc[2]*inv, acc[3]*inv);
            *(float4*)&xv[w][cq * 8 + 4] = make_float4(acc[4]*inv, acc[5]*inv, acc[6]*inv, acc[7]*inv);
        }
        __syncwarp();
        float o = bs[lane];
#pragma unroll
        for (int i = 0; i < 32; i++) o = fmaf(xv[w][i], Ws[i * 32 + lane], o);
        __syncwarp();
        fsum += o;
        fsq  = fmaf(o, o, fsq);
        float onb = __shfl_xor_sync(0xffffffffu, o, 1);
        if ((lane & 1) == 0) {
            __half2 hv = __floats2half2_rn(o, onb);
            ((__half2*)out)[(size_t)v * 16 + (lane >> 1)] = hv;
        }
    }
    atomicAdd(&ssum[lane], (double)fsum);
    atomicAdd(&ssq[lane],  (double)fsq);
    __syncthreads();
    if (t < 32) {
        atomicAdd(&statsOut[t],      ssum[t]);
        atomicAdd(&statsOut[32 + t], ssq[t]);
    }
}

// ---- fold: z[v] = BN(x3[v]) . W3  (warp per node, lane=channel) ----
__global__ void fold_kernel(const __half* __restrict__ x3,
                            const double* __restrict__ statsIn,
                            const float* __restrict__ gIn, const float* __restrict__ bIn,
                            const float* __restrict__ W3,
                            float* __restrict__ z, int n) {
    __shared__ float As[32], Bs[32], Wsh[32];
    int t = threadIdx.x;
    if (t < 32) {
        double m   = statsIn[t] / (double)n;
        double var = statsIn[32 + t] / (double)n - m * m;
        float  rs  = rsqrtf((float)var + EPS);
        float  A   = gIn[t] * rs;
        As[t] = A;
        Bs[t] = bIn[t] - (float)m * A;
        Wsh[t] = W3[t];
    }
    __syncthreads();
    int w = t >> 5, lane = t & 31;
    int v = blockIdx.x * 8 + w;
    if (v >= n) return;
    float val = __half2float(x3[(size_t)v * 32 + lane]);
    val = fmaxf(fmaf(As[lane], val, Bs[lane]), 0.f) * Wsh[lane];
#pragma unroll
    for (int off = 16; off; off >>= 1) val += __shfl_down_sync(0xffffffffu, val, off);
    if (lane == 0) z[v] = val;
}

// ---- layer 4: scalar mean-gather of z + bias + stats (fp32 partials) ----
__global__ void __launch_bounds__(512, 2)
layer4_kernel(const float* __restrict__ z, const int* __restrict__ rp,
              const int* __restrict__ ci, const float* __restrict__ b3,
              float* __restrict__ out, int n, double* __restrict__ statsOut) {
    __shared__ double ssum, ssq;
    int t = threadIdx.x;
    if (t == 0) { ssum = 0.0; ssq = 0.0; }
    __syncthreads();
    int w = t >> 5, lane = t & 31;
    int warpsTotal = gridDim.x * 16;
    int wg = blockIdx.x * 16 + w;
    float bias = b3[0];
    float fsum = 0.f, fsq = 0.f;
    for (int v = wg; v < n; v += warpsTotal) {
        int beg = __ldg(&rp[v]), end = __ldg(&rp[v + 1]);
        float s = 0.f;
        for (int j = beg + lane; j < end; j += 32) s += z[__ldg(&ci[j])];
#pragma unroll
        for (int off = 16; off; off >>= 1) s += __shfl_down_sync(0xffffffffu, s, off);
        if (lane == 0) {
            float o = s / fmaxf((float)(end - beg), 1.0f) + bias;
            out[v] = o;
            fsum += o;
            fsq  = fmaf(o, o, fsq);
        }
    }
    if (lane == 0) {
        atomicAdd(&ssum, (double)fsum);
        atomicAdd(&ssq,  (double)fsq);
    }
    __syncthreads();
    if (t == 0) {
        atomicAdd(&statsOut[0],  ssum);
        atomicAdd(&statsOut[32], ssq);
    }
}

// ---- fused per-graph mean pool (BN on the fly; x1..x3 fp16) + MLP head ----
__global__ void pool_mlp_kernel(const float* __restrict__ h,  const __half* __restrict__ x1,
                                const __half* __restrict__ x2, const __half* __restrict__ x3,
                                const float* __restrict__ x4, const int* __restrict__ gp,
                                const double* __restrict__ stats,
                                const float* __restrict__ g0, const float* __restrict__ be0,
                                const float* __restrict__ g1, const float* __restrict__ be1,
                                const float* __restrict__ g2, const float* __restrict__ be2,
                                const float* __restrict__ g3, const float* __restrict__ be3,
                                const float* __restrict__ W0, const float* __restrict__ b0,
                                const float* __restrict__ W1, const float* __restrict__ b1,
                                const float* __restrict__ W2, const float* __restrict__ b2,
                                float* __restrict__ out, int n) {
    __shared__ float As[97], Bs[97];
    __shared__ float hr[129];
    __shared__ float l0[128];
    __shared__ float l1[64];
    int t = threadIdx.x;
    if (t < 97) {
        int layer = (t < 96) ? (t >> 5) : 3;
        int c     = (t < 96) ? (t & 31) : 0;
        const double* st = stats + layer * 64;
        const float* gg = (layer == 0) ? g0 : (layer == 1) ? g1 : (layer == 2) ? g2 : g3;
        const float* bb = (layer == 0) ? be0 : (layer == 1) ? be1 : (layer == 2) ? be2 : be3;
        double m   = st[c] / (double)n;
        double var = st[32 + c] / (double)n - m * m;
        float  rs  = rsqrtf((float)var + EPS);
        float  A   = gg[c] * rs;
        As[t] = A;
        Bs[t] = bb[c] - (float)m * A;
    }
    __syncthreads();
    int g = blockIdx.x;
    int beg = gp[g], end = gp[g + 1];
    float inv = 1.0f / fmaxf((float)(end - beg), 1.0f);
    int w = t >> 5, c = t & 31;
    {
        float s = 0.f;
        if (w == 0) {
            int v = beg;
            for (; v + 4 <= end; v += 4) {
                float a = h[v * 32 + c],       b = h[(v + 1) * 32 + c];
                float d = h[(v + 2) * 32 + c], e = h[(v + 3) * 32 + c];
                s += (a + b) + (d + e);
            }
            for (; v < end; v++) s += h[v * 32 + c];
        } else {
            const __half* p = (w == 1) ? x1 : (w == 2) ? x2 : x3;
            float A = As[(w - 1) * 32 + c];
            float B = Bs[(w - 1) * 32 + c];
            int v = beg;
            for (; v + 4 <= end; v += 4) {
                float a = __half2float(p[(size_t)v * 32 + c]);
                float b = __half2float(p[(size_t)(v + 1) * 32 + c]);
                float d = __half2float(p[(size_t)(v + 2) * 32 + c]);
                float e = __half2float(p[(size_t)(v + 3) * 32 + c]);
                a = fmaxf(fmaf(A, a, B), 0.f); b = fmaxf(fmaf(A, b, B), 0.f);
                d = fmaxf(fmaf(A, d, B), 0.f); e = fmaxf(fmaf(A, e, B), 0.f);
                s += (a + b) + (d + e);
            }
            for (; v < end; v++) s += fmaxf(fmaf(A, __half2float(p[(size_t)v * 32 + c]), B), 0.f);
        }
        hr[t] = s * inv;
    }
    if (t == 0) {
        float A = As[96], B = Bs[96];
        float s = 0.f;
        int v = beg;
        for (; v + 4 <= end; v += 4) {
            float a = fmaxf(fmaf(A, x4[v], B), 0.f);
            float b = fmaxf(fmaf(A, x4[v + 1], B), 0.f);
            float d = fmaxf(fmaf(A, x4[v + 2], B), 0.f);
            float e = fmaxf(fmaf(A, x4[v + 3], B), 0.f);
            s += (a + b) + (d + e);
        }
        for (; v < end; v++) s += fmaxf(fmaf(A, x4[v], B), 0.f);
        hr[128] = s * inv;
    }
    __syncthreads();
    {
        float acc = b0[t];
#pragma unroll 4
        for (int i = 0; i < 129; i++) acc = fmaf(hr[i], W0[i * 128 + t], acc);
        l0[t] = fmaxf(acc, 0.0f);
    }
    __syncthreads();
    if (t < 64) {
        float acc = b1[t];
#pragma unroll 4
        for (int i = 0; i < 128; i++) acc = fmaf(l0[i], W1[i * 64 + t], acc);
        l1[t] = fmaxf(acc, 0.0f);
    }
    __syncthreads();
    if (t == 0) {
        float acc = b2[0];
        for (int i = 0; i < 64; i++) acc = fmaf(l1[i], W2[i], acc);
        out[g] = acc;
    }
}

extern "C" void kernel_launch(void* const* d_in, const int* in_sizes, int n_in,
                              void* d_out, int out_size) {
    const float* h   = (const float*)d_in[0];
    const int*   src = (const int*)d_in[1];
    const int*   dst = (const int*)d_in[2];
    const int*   gid = (const int*)d_in[3];
    const int E = in_sizes[1];
    const int N = in_sizes[3];
    const int G = out_size;
    float* out = (float*)d_out;

    const float* cw[4]; const float* cb[4]; const float* bg[4]; const float* bb[4];
    for (int i = 0; i < 4; i++) {
        cw[i] = (const float*)d_in[4 + 4 * i + 0];
        cb[i] = (const float*)d_in[4 + 4 * i + 1];
        bg[i] = (const float*)d_in[4 + 4 * i + 2];
        bb[i] = (const float*)d_in[4 + 4 * i + 3];
    }
    const float* W0 = (const float*)d_in[20];
    const float* b0 = (const float*)d_in[21];
    const float* W1 = (const float*)d_in[22];
    const float* b1 = (const float*)d_in[23];
    const float* W2 = (const float*)d_in[24];
    const float* b2 = (const float*)d_in[25];

    int *hist, *rp, *pos, *ci, *gp, *bsum;
    __half *h16, *x1, *x2, *x3;
    float *x4, *z;
    double *stats;
    cudaGetSymbolAddress((void**)&hist,  g_hist);
    cudaGetSymbolAddress((void**)&rp,    g_rp);
    cudaGetSymbolAddress((void**)&pos,   g_pos);
    cudaGetSymbolAddress((void**)&ci,    g_ci);
    cudaGetSymbolAddress((void**)&gp,    g_gp);
    cudaGetSymbolAddress((void**)&bsum,  g_bsum);
    cudaGetSymbolAddress((void**)&h16,   g_h16);
    cudaGetSymbolAddress((void**)&x1,    g_x1);
    cudaGetSymbolAddress((void**)&x2,    g_x2);
    cudaGetSymbolAddress((void**)&x3,    g_x3);
    cudaGetSymbolAddress((void**)&x4,    g_x4);
    cudaGetSymbolAddress((void**)&z,     g_z);
    cudaGetSymbolAddress((void**)&stats, g_stats);

    const int T = 256;
    const int n8 = N * 4;  // N*32/8 uint4-sized conversion items

    // ---- CSR build (g_hist and g_stats arrive zeroed: load-init / self-cleaned) ----
    int combo = max(E, n8);
    hist_h2half_kernel<<<(combo + T - 1) / T, T>>>(dst, hist, E, h, h16, n8);
    int nb = (N + SBS - 1) / SBS;
    scan_p1<<<nb, SBS>>>(hist, bsum, N);
    scan_p2<<<1, 1024>>>(bsum, nb, stats);            // + zero stats
    scan_p3<<<nb, SBS>>>(hist, bsum, rp, pos, N);     // + re-zero hist
    fill_kernel<<<(E + T - 1) / T, T>>>(src, dst, pos, ci, E);

    // ---- GCN layers ----
    const int LG = 296, LT = 512;
    gcn_layer32h<false><<<LG, LT>>>(h16, rp, ci, cw[0], cb[0],
                                    nullptr, nullptr, nullptr,
                                    x1, N, stats + 0 * 64);
    gcn_layer32h<true><<<LG, LT>>>(x1, rp, ci, cw[1], cb[1],
                                   stats + 0 * 64, bg[0], bb[0],
                                   x2, N, stats + 1 * 64);
    gcn_layer32h<true><<<LG, LT>>>(x2, rp, ci, cw[2], cb[2],
                                   stats + 1 * 64, bg[1], bb[1],
                                   x3, N, stats + 2 * 64);
    fold_kernel<<<(N + 7) / 8, 256>>>(x3, stats + 2 * 64, bg[2], bb[2], cw[3], z, N);
    layer4_kernel<<<LG, LT>>>(z, rp, ci, cb[3], x4, N, stats + 3 * 64);

    // ---- graph ranges + fused pool + MLP ----
    graph_ptr_kernel<<<(N + 1 + T - 1) / T, T>>>(gid, gp, N, G);
    pool_mlp_kernel<<<G, 128>>>(h, x1, x2, x3, x4, gp, stats,
                                bg[0], bb[0], bg[1], bb[1], bg[2], bb[2], bg[3], bb[3],
                                W0, b0, W1, b1, W2, b2, out, N);
}